// round 10
// baseline (speedup 1.0000x reference)
#include <cuda_runtime.h>
#include <stdint.h>

// Hadamard on qubit TARGET=5 of a 24-qubit real fp32 statevector, batch 2.
// Pair partner at element-stride 2^18 => float4-stride 2^16 (STEP).
// 2^23 float4s total, 2^22 pairs. Each thread handles EIGHT pairs:
// 16 independent LDG.128 front-batched (MLP=16), grid-split into eight
// widely separated streams so every access stays perfectly coalesced.
// Streaming hints (.cs) since no byte is ever reused.

__global__ void __launch_bounds__(256) hadamard_q5_kernel(
    const float4* __restrict__ in, float4* __restrict__ out)
{
    const unsigned t = blockIdx.x * blockDim.x + threadIdx.x;  // [0, 2^19)
    const float s = 0.70710678118654752440f;
    const unsigned STEP = 1u << 16;

    unsigned base[8];
#pragma unroll
    for (int k = 0; k < 8; k++) {
        const unsigned p = t + ((unsigned)k << 19);
        base[k] = ((p >> 16) << 17) + (p & 0xFFFFu);
    }

    // Front-batch all sixteen loads (MLP=16), evict-first.
    float4 A[8], B[8];
#pragma unroll
    for (int k = 0; k < 8; k++) A[k] = __ldcs(in + base[k]);
#pragma unroll
    for (int k = 0; k < 8; k++) B[k] = __ldcs(in + base[k] + STEP);

#pragma unroll
    for (int k = 0; k < 8; k++) {
        float4 u, v;
        u.x = (A[k].x + B[k].x) * s;  v.x = (A[k].x - B[k].x) * s;
        u.y = (A[k].y + B[k].y) * s;  v.y = (A[k].y - B[k].y) * s;
        u.z = (A[k].z + B[k].z) * s;  v.z = (A[k].z - B[k].z) * s;
        u.w = (A[k].w + B[k].w) * s;  v.w = (A[k].w - B[k].w) * s;
        __stcs(out + base[k], u);
        __stcs(out + base[k] + STEP, v);
    }
}

extern "C" void kernel_launch(void* const* d_in, const int* in_sizes, int n_in,
                              void* d_out, int out_size)
{
    const float4* in  = (const float4*)d_in[0];
    float4*       out = (float4*)d_out;

    // 2^22 pairs, 8 pairs/thread -> 2^19 threads -> 2048 blocks of 256
    const unsigned threads = 256;
    const unsigned blocks  = (1u << 19) / threads;  // 2048

    hadamard_q5_kernel<<<blocks, threads>>>(in, out);
}